// round 5
// baseline (speedup 1.0000x reference)
#include <cuda_runtime.h>
#include <math.h>

#define N_ 8
#define C_ 512
#define H_ 64
#define W_ 64

typedef unsigned long long ull;

__device__ __forceinline__ ull pack2(float lo, float hi) {
    ull r; asm("mov.b64 %0, {%1, %2};" : "=l"(r) : "f"(lo), "f"(hi)); return r;
}
__device__ __forceinline__ void unpack2(ull v, float& lo, float& hi) {
    asm("mov.b64 {%0, %1}, %2;" : "=f"(lo), "=f"(hi) : "l"(v));
}
__device__ __forceinline__ ull fma2(ull a, ull b, ull c) {
    ull d; asm("fma.rn.f32x2 %0, %1, %2, %3;" : "=l"(d) : "l"(a), "l"(b), "l"(c)); return d;
}
__device__ __forceinline__ ull mul2(ull a, ull b) {
    ull d; asm("mul.rn.f32x2 %0, %1, %2;" : "=l"(d) : "l"(a), "l"(b)); return d;
}
__device__ __forceinline__ ull add2(ull a, ull b) {
    ull d; asm("add.rn.f32x2 %0, %1, %2;" : "=l"(d) : "l"(a), "l"(b)); return d;
}

// off_w transposed AND duplicated: g_offw_d[c*32 + o] = (w, w) as f32x2
__device__ __align__(16) ull g_offw_d[C_ * 32];

__global__ void transpose_offw_kernel(const float* __restrict__ off_w) {
    int i = blockIdx.x * 1024 + threadIdx.x;   // 16 x 1024 = 16384
    int o = i >> 9;
    int c = i & 511;
    float w = off_w[i];
    g_offw_d[c * 32 + o] = pack2(w, w);
}

// Shared memory (floats), per CTA of 512 threads covering 32 pixels:
//   region0 : 16896  (x1 [512][32] A-D; stage [512][33] E/F)
//   offsP   : 8192   (A/B: psum+psq alias; D: 8 partial slots [8][32o][32w];
//                     after reduce: offs in [0:1024]; sp in [1024:5120])
//   mu,rs   : 64
#define SMEM_FLOATS (16896 + 8192 + 64)

__global__ __launch_bounds__(512, 2)
void das_fused_kernel(const float* __restrict__ in0,   // input_first NCHW
                      const float* __restrict__ inL,   // input_last  NHWC
                      const float* __restrict__ dw_w,  // [C,1,3,3]
                      const float* __restrict__ dw_b,  // [C]
                      const float* __restrict__ ln_g,  // [C]
                      const float* __restrict__ ln_b,  // [C]
                      const float* __restrict__ off_b, // [2G]
                      float* __restrict__ out)         // NCHW
{
    extern __shared__ float sm[];
    float* x1    = sm;                 // stride 32 rows (A-D)
    float* stage = sm;                 // stride 33 rows (E-F)
    float* offsP = sm + 16896;         // 8192
    float* psum  = offsP;              // 512 (alias, dead before D)
    float* psq   = offsP + 512;        // 512
    float* sp    = offsP + 1024;       // 4096 sample params (E)
    float* mu    = sm + 16896 + 8192;  // 32
    float* rs    = mu + 32;            // 32

    const int t     = threadIdx.x;
    const int half  = blockIdx.x;      // 0 or 1
    const int h     = blockIdx.y;
    const int n     = blockIdx.z;
    const int wbase = half * 32;

    const int w4   = t & 7;            // w-quad within the 32 pixels
    const int cgrp = t >> 3;           // 0..63, 8 channels each
    const int lane = t & 31;

    // ======== Phase A: depthwise 3x3 conv + bias + LN partials ==============
    float s0 = 0.f, s1 = 0.f, s2 = 0.f, s3 = 0.f;
    float q0 = 0.f, q1 = 0.f, q2 = 0.f, q3 = 0.f;

    const float* in_n = in0 + (size_t)n * C_ * H_ * W_;

    #pragma unroll 4
    for (int i = 0; i < 8; ++i) {
        int c = cgrp * 8 + i;
        const float* wp = dw_w + c * 9;
        const float* cp = in_n + (size_t)c * H_ * W_;
        float b = dw_b[c];
        float a0 = b, a1 = b, a2 = b, a3 = b;
        #pragma unroll
        for (int dy = -1; dy <= 1; ++dy) {
            int hy = h + dy;
            if ((unsigned)hy < (unsigned)H_) {          // uniform across block
                const float* r = cp + hy * W_ + wbase + w4 * 4;
                float4 v = *(const float4*)r;
                float lf = __shfl_up_sync(0xffffffffu, v.w, 1, 8);
                if (w4 == 0) lf = (wbase > 0) ? r[-1] : 0.f;
                float rt = __shfl_down_sync(0xffffffffu, v.x, 1, 8);
                if (w4 == 7) rt = (wbase + 32 < W_) ? r[4] : 0.f;
                float k0 = wp[(dy + 1) * 3 + 0];
                float k1 = wp[(dy + 1) * 3 + 1];
                float k2 = wp[(dy + 1) * 3 + 2];
                a0 += k0 * lf  + k1 * v.x + k2 * v.y;
                a1 += k0 * v.x + k1 * v.y + k2 * v.z;
                a2 += k0 * v.y + k1 * v.z + k2 * v.w;
                a3 += k0 * v.z + k1 * v.w + k2 * rt;
            }
        }
        s0 += a0; q0 += a0 * a0;
        s1 += a1; q1 += a1 * a1;
        s2 += a2; q2 += a2 * a2;
        s3 += a3; q3 += a3 * a3;
        *(float4*)(x1 + c * 32 + w4 * 4) = make_float4(a0, a1, a2, a3);
    }

    s0 += __shfl_xor_sync(0xffffffffu, s0, 8);
    s0 += __shfl_xor_sync(0xffffffffu, s0, 16);
    s1 += __shfl_xor_sync(0xffffffffu, s1, 8);
    s1 += __shfl_xor_sync(0xffffffffu, s1, 16);
    s2 += __shfl_xor_sync(0xffffffffu, s2, 8);
    s2 += __shfl_xor_sync(0xffffffffu, s2, 16);
    s3 += __shfl_xor_sync(0xffffffffu, s3, 8);
    s3 += __shfl_xor_sync(0xffffffffu, s3, 16);
    q0 += __shfl_xor_sync(0xffffffffu, q0, 8);
    q0 += __shfl_xor_sync(0xffffffffu, q0, 16);
    q1 += __shfl_xor_sync(0xffffffffu, q1, 8);
    q1 += __shfl_xor_sync(0xffffffffu, q1, 16);
    q2 += __shfl_xor_sync(0xffffffffu, q2, 8);
    q2 += __shfl_xor_sync(0xffffffffu, q2, 16);
    q3 += __shfl_xor_sync(0xffffffffu, q3, 8);
    q3 += __shfl_xor_sync(0xffffffffu, q3, 16);
    {
        int warpId = t >> 5;
        if (lane < 8) {
            psum[warpId * 32 + lane * 4 + 0] = s0;
            psum[warpId * 32 + lane * 4 + 1] = s1;
            psum[warpId * 32 + lane * 4 + 2] = s2;
            psum[warpId * 32 + lane * 4 + 3] = s3;
            psq [warpId * 32 + lane * 4 + 0] = q0;
            psq [warpId * 32 + lane * 4 + 1] = q1;
            psq [warpId * 32 + lane * 4 + 2] = q2;
            psq [warpId * 32 + lane * 4 + 3] = q3;
        }
    }
    __syncthreads();

    // ======== Phase B: finish LN statistics (32 pixels) =====================
    if (t < 32) {
        float s = 0.f, q = 0.f;
        #pragma unroll
        for (int j = 0; j < 16; ++j) {
            s += psum[j * 32 + t];
            q += psq [j * 32 + t];
        }
        float m = s * (1.0f / 512.0f);
        float var = q * (1.0f / 512.0f) - m * m;
        mu[t] = m;
        rs[t] = rsqrtf(var + 1e-6f);
    }
    __syncthreads();

    // ======== Phase C: LN + exact GELU (erf form), in place ==================
    {
        float4 m4 = *(const float4*)(mu + w4 * 4);
        float4 r4 = *(const float4*)(rs + w4 * 4);
        #pragma unroll 2
        for (int i = 0; i < 8; ++i) {
            int c = cgrp * 8 + i;
            float gg = ln_g[c];
            float bb = ln_b[c];
            float4 y = *(const float4*)(x1 + c * 32 + w4 * 4);
            y.x = (y.x - m4.x) * r4.x * gg + bb;
            y.y = (y.y - m4.y) * r4.y * gg + bb;
            y.z = (y.z - m4.z) * r4.z * gg + bb;
            y.w = (y.w - m4.w) * r4.w * gg + bb;
            y.x = 0.5f * y.x * (1.0f + erff(y.x * 0.70710678118654752f));
            y.y = 0.5f * y.y * (1.0f + erff(y.y * 0.70710678118654752f));
            y.z = 0.5f * y.z * (1.0f + erff(y.z * 0.70710678118654752f));
            y.w = 0.5f * y.w * (1.0f + erff(y.w * 0.70710678118654752f));
            *(float4*)(x1 + c * 32 + w4 * 4) = y;
        }
    }
    __syncthreads();

    // ======== Phase D: offset projection, 8o x 4w tiles, f32x2, dup weights ==
    {
        const int g4   = t & 7;          // w-quad
        const int og   = (t >> 3) & 3;   // o-oct: o = og*8 .. og*8+7
        const int part = t >> 5;         // 0..15, 32 channels each
        ull acc[16];                     // [o][lo/hi]
        #pragma unroll
        for (int i = 0; i < 16; ++i) acc[i] = 0ull;
        const int cb = part * 32;
        const ull* wdp = g_offw_d + og * 8;
        #pragma unroll 2
        for (int ci = 0; ci < 32; ++ci) {
            int c = cb + ci;
            ulonglong2 xv = *(const ulonglong2*)(x1 + c * 32 + g4 * 4);
            const ulonglong2* wp2 = (const ulonglong2*)(wdp + c * 32);
            ulonglong2 w01 = wp2[0];
            ulonglong2 w23 = wp2[1];
            acc[0]  = fma2(w01.x, xv.x, acc[0]);  acc[1]  = fma2(w01.x, xv.y, acc[1]);
            acc[2]  = fma2(w01.y, xv.x, acc[2]);  acc[3]  = fma2(w01.y, xv.y, acc[3]);
            acc[4]  = fma2(w23.x, xv.x, acc[4]);  acc[5]  = fma2(w23.x, xv.y, acc[5]);
            acc[6]  = fma2(w23.y, xv.x, acc[6]);  acc[7]  = fma2(w23.y, xv.y, acc[7]);
            ulonglong2 w45 = wp2[2];
            ulonglong2 w67 = wp2[3];
            acc[8]  = fma2(w45.x, xv.x, acc[8]);  acc[9]  = fma2(w45.x, xv.y, acc[9]);
            acc[10] = fma2(w45.y, xv.x, acc[10]); acc[11] = fma2(w45.y, xv.y, acc[11]);
            acc[12] = fma2(w67.x, xv.x, acc[12]); acc[13] = fma2(w67.x, xv.y, acc[13]);
            acc[14] = fma2(w67.y, xv.x, acc[14]); acc[15] = fma2(w67.y, xv.y, acc[15]);
        }
        const int slot = part & 7;
        float* pp = offsP + slot * 1024 + (og * 8) * 32 + g4 * 4;
        if (part < 8) {
            #pragma unroll
            for (int o = 0; o < 8; ++o) {
                ((ull*)(pp + o * 32))[0] = acc[o * 2];
                ((ull*)(pp + o * 32))[1] = acc[o * 2 + 1];
            }
        }
        __syncthreads();
        if (part >= 8) {
            #pragma unroll
            for (int o = 0; o < 8; ++o) {
                ull* dst = (ull*)(pp + o * 32);
                dst[0] = add2(dst[0], acc[o * 2]);
                dst[1] = add2(dst[1], acc[o * 2 + 1]);
            }
        }
    }
    __syncthreads();

    // reduce 8 slots -> offs in offsP[0:1024], add bias
    {
        #pragma unroll
        for (int r = 0; r < 2; ++r) {
            int idx = t + r * 512;
            int o = idx >> 5;
            float s = offsP[idx];
            #pragma unroll
            for (int p = 1; p < 8; ++p) s += offsP[p * 1024 + idx];
            offsP[idx] = s + __ldg(off_b + o);
        }
    }
    __syncthreads();

    // ======== Phase E0: per-sample bilinear params ===========================
    {
        const int S = t;            // 0..511
        const int g = S >> 5;
        const int w = S & 31;
        float px = (float)(wbase + w) + offsP[(2 * g + 0) * 32 + w];
        float py = (float)h           + offsP[(2 * g + 1) * 32 + w];
        float x0f = floorf(px);
        float y0f = floorf(py);
        float fx = px - x0f;
        float fy = py - y0f;
        int x0 = (int)x0f;
        int y0 = (int)y0f;
        float vx0 = (x0f >= 0.f       && x0f <= 63.f)       ? 1.f : 0.f;
        float vx1 = (x0f + 1.f >= 0.f && x0f + 1.f <= 63.f) ? 1.f : 0.f;
        float vy0 = (y0f >= 0.f       && y0f <= 63.f)       ? 1.f : 0.f;
        float vy1 = (y0f + 1.f >= 0.f && y0f + 1.f <= 63.f) ? 1.f : 0.f;
        int xc0 = min(max(x0, 0), 63);
        int xc1 = min(max(x0 + 1, 0), 63);
        int yc0 = min(max(y0, 0), 63);
        int yc1 = min(max(y0 + 1, 0), 63);
        float* q = sp + S * 8;
        q[0] = (1.f - fx) * (1.f - fy) * vx0 * vy0;
        q[1] = fx * (1.f - fy) * vx1 * vy0;
        q[2] = (1.f - fx) * fy * vx0 * vy1;
        q[3] = fx * fy * vx1 * vy1;
        int* qi = (int*)(q + 4);
        qi[0] = (yc0 * 64 + xc0) * 512;
        qi[1] = (yc0 * 64 + xc1) * 512;
        qi[2] = (yc1 * 64 + xc0) * 512;
        qi[3] = (yc1 * 64 + xc1) * 512;
    }
    __syncthreads();

    // ======== Phase E: coalesced bilinear gather (8 lanes per sample) =======
    {
        const int wp = t >> 5;        // warp 0..15
        const int s  = (t >> 3) & 3;  // sample within warp
        const int e  = t & 7;         // quad within GC=32
        const float* inL_n = inL + (size_t)n * H_ * W_ * C_;
        #pragma unroll
        for (int k = 0; k < 8; ++k) {
            int S = k * 64 + wp * 4 + s;    // 0..511
            int g = S >> 5;
            int w = S & 31;
            float4 wgt = *(const float4*)(sp + S * 8);
            int4  ofs  = *(const int4*) (sp + S * 8 + 4);
            const float* bp = inL_n + g * 32 + e * 4;
            ulonglong2 a = *(const ulonglong2*)(bp + ofs.x);
            ulonglong2 b = *(const ulonglong2*)(bp + ofs.y);
            ulonglong2 c = *(const ulonglong2*)(bp + ofs.z);
            ulonglong2 d = *(const ulonglong2*)(bp + ofs.w);
            ull w00 = pack2(wgt.x, wgt.x);
            ull w10 = pack2(wgt.y, wgt.y);
            ull w01 = pack2(wgt.z, wgt.z);
            ull w11 = pack2(wgt.w, wgt.w);
            ull rlo = mul2(w00, a.x);
            rlo = fma2(w10, b.x, rlo);
            rlo = fma2(w01, c.x, rlo);
            rlo = fma2(w11, d.x, rlo);
            ull rhi = mul2(w00, a.y);
            rhi = fma2(w10, b.y, rhi);
            rhi = fma2(w01, c.y, rhi);
            rhi = fma2(w11, d.y, rhi);
            float r0, r1, r2, r3;
            unpack2(rlo, r0, r1);
            unpack2(rhi, r2, r3);
            int crow = g * 32 + e * 4;
            stage[(crow + 0) * 33 + w] = r0;
            stage[(crow + 1) * 33 + w] = r1;
            stage[(crow + 2) * 33 + w] = r2;
            stage[(crow + 3) * 33 + w] = r3;
        }
    }
    __syncthreads();

    // ======== Phase F: coalesced copy-out ====================================
    {
        float* outp = out + (size_t)n * C_ * H_ * W_ + (size_t)h * W_ + wbase;
        #pragma unroll
        for (int k = 0; k < 8; ++k) {
            int c = (t >> 3) + k * 64;
            float4 r;
            r.x = stage[c * 33 + w4 * 4 + 0];
            r.y = stage[c * 33 + w4 * 4 + 1];
            r.z = stage[c * 33 + w4 * 4 + 2];
            r.w = stage[c * 33 + w4 * 4 + 3];
            *(float4*)(outp + (size_t)c * (H_ * W_) + w4 * 4) = r;
        }
    }
}

extern "C" void kernel_launch(void* const* d_in, const int* in_sizes, int n_in,
                              void* d_out, int out_size)
{
    (void)in_sizes; (void)n_in; (void)out_size;
    const float* in0   = (const float*)d_in[0];
    const float* inL   = (const float*)d_in[1];
    const float* dw_w  = (const float*)d_in[2];
    const float* dw_b  = (const float*)d_in[3];
    const float* ln_g  = (const float*)d_in[4];
    const float* ln_b  = (const float*)d_in[5];
    const float* off_w = (const float*)d_in[6];
    const float* off_b = (const float*)d_in[7];
    float* out = (float*)d_out;

    transpose_offw_kernel<<<16, 1024>>>(off_w);

    const int smem_bytes = SMEM_FLOATS * sizeof(float);   // 100608
    cudaFuncSetAttribute(das_fused_kernel,
                         cudaFuncAttributeMaxDynamicSharedMemorySize, smem_bytes);

    dim3 grid(2, H_, N_);
    das_fused_kernel<<<grid, 512, smem_bytes>>>(in0, inL, dw_w, dw_b,
                                                ln_g, ln_b, off_b, out);
}

// round 6
// speedup vs baseline: 1.1867x; 1.1867x over previous
#include <cuda_runtime.h>
#include <math.h>

#define N_ 8
#define C_ 512
#define H_ 64
#define W_ 64

typedef unsigned long long ull;

__device__ __forceinline__ ull pack2(float lo, float hi) {
    ull r; asm("mov.b64 %0, {%1, %2};" : "=l"(r) : "f"(lo), "f"(hi)); return r;
}
__device__ __forceinline__ void unpack2(ull v, float& lo, float& hi) {
    asm("mov.b64 {%0, %1}, %2;" : "=f"(lo), "=f"(hi) : "l"(v));
}
__device__ __forceinline__ ull fma2(ull a, ull b, ull c) {
    ull d; asm("fma.rn.f32x2 %0, %1, %2, %3;" : "=l"(d) : "l"(a), "l"(b), "l"(c)); return d;
}
__device__ __forceinline__ ull mul2(ull a, ull b) {
    ull d; asm("mul.rn.f32x2 %0, %1, %2;" : "=l"(d) : "l"(a), "l"(b)); return d;
}
__device__ __forceinline__ float tanh_ap(float x) {
    float r; asm("tanh.approx.f32 %0, %1;" : "=f"(r) : "f"(x)); return r;
}
// tanh-form GELU: 0.5*x*(1+tanh(0.79788456*(x + 0.044715*x^3)))
__device__ __forceinline__ float gelu_fast(float x) {
    float x2 = x * x;
    float u  = x * fmaf(0.0356774081f, x2, 0.7978845608f);
    float t  = tanh_ap(u);
    return 0.5f * x * (1.0f + t);
}

// off_w transposed to [c][o] (o fastest, float4 groups of 4 o's)
__device__ float g_offw_t[C_ * 32];

__global__ void transpose_offw_kernel(const float* __restrict__ off_w) {
    int i = blockIdx.x * 1024 + threadIdx.x;   // 16 x 1024 = 16384
    int o = i >> 9;
    int c = i & 511;
    g_offw_t[c * 32 + o] = off_w[i];
}

// Shared memory (floats), per CTA of 512 threads covering 32 pixels:
//   region0 : 16896  (x1 [512][32] A-D; stage [512][33] E/F)
//   offsP   : 8192   (A/B: psum+psq alias; D: 8 partial tiles; after reduce:
//                     offs in [0:1024]; sp in [1024:5120])
//   mu,rs   : 64
#define SMEM_FLOATS (16896 + 8192 + 64)

__global__ __launch_bounds__(512, 2)
void das_fused_kernel(const float* __restrict__ in0,   // input_first NCHW
                      const float* __restrict__ inL,   // input_last  NHWC
                      const float* __restrict__ dw_w,  // [C,1,3,3]
                      const float* __restrict__ dw_b,  // [C]
                      const float* __restrict__ ln_g,  // [C]
                      const float* __restrict__ ln_b,  // [C]
                      const float* __restrict__ off_b, // [2G]
                      float* __restrict__ out)         // NCHW
{
    extern __shared__ float sm[];
    float* x1    = sm;                 // stride 32 rows (A-D)
    float* stage = sm;                 // stride 33 rows (E-F)
    float* offsP = sm + 16896;         // 8192
    float* psum  = offsP;              // 512 (alias, dead before D)
    float* psq   = offsP + 512;        // 512
    float* sp    = offsP + 1024;       // 4096 sample params (E)
    float* mu    = sm + 16896 + 8192;  // 32
    float* rs    = mu + 32;            // 32

    const int t     = threadIdx.x;
    const int half  = blockIdx.x;      // 0 or 1
    const int h     = blockIdx.y;
    const int n     = blockIdx.z;
    const int wbase = half * 32;

    const int w4   = t & 7;            // w-quad within the 32 pixels
    const int cgrp = t >> 3;           // 0..63, 8 channels each
    const int lane = t & 31;

    // ======== Phase A: depthwise 3x3 conv + bias + LN partials ==============
    float s0 = 0.f, s1 = 0.f, s2 = 0.f, s3 = 0.f;
    float q0 = 0.f, q1 = 0.f, q2 = 0.f, q3 = 0.f;

    const float* in_n = in0 + (size_t)n * C_ * H_ * W_;

    #pragma unroll 4
    for (int i = 0; i < 8; ++i) {
        int c = cgrp * 8 + i;
        const float* wp = dw_w + c * 9;
        const float* cp = in_n + (size_t)c * H_ * W_;
        float b = dw_b[c];
        float a0 = b, a1 = b, a2 = b, a3 = b;
        #pragma unroll
        for (int dy = -1; dy <= 1; ++dy) {
            int hy = h + dy;
            if ((unsigned)hy < (unsigned)H_) {          // uniform across block
                const float* r = cp + hy * W_ + wbase + w4 * 4;
                float4 v = *(const float4*)r;
                float lf = __shfl_up_sync(0xffffffffu, v.w, 1, 8);
                if (w4 == 0) lf = (wbase > 0) ? r[-1] : 0.f;
                float rt = __shfl_down_sync(0xffffffffu, v.x, 1, 8);
                if (w4 == 7) rt = (wbase + 32 < W_) ? r[4] : 0.f;
                float k0 = wp[(dy + 1) * 3 + 0];
                float k1 = wp[(dy + 1) * 3 + 1];
                float k2 = wp[(dy + 1) * 3 + 2];
                a0 += k0 * lf  + k1 * v.x + k2 * v.y;
                a1 += k0 * v.x + k1 * v.y + k2 * v.z;
                a2 += k0 * v.y + k1 * v.z + k2 * v.w;
                a3 += k0 * v.z + k1 * v.w + k2 * rt;
            }
        }
        s0 += a0; q0 += a0 * a0;
        s1 += a1; q1 += a1 * a1;
        s2 += a2; q2 += a2 * a2;
        s3 += a3; q3 += a3 * a3;
        *(float4*)(x1 + c * 32 + w4 * 4) = make_float4(a0, a1, a2, a3);
    }

    s0 += __shfl_xor_sync(0xffffffffu, s0, 8);
    s0 += __shfl_xor_sync(0xffffffffu, s0, 16);
    s1 += __shfl_xor_sync(0xffffffffu, s1, 8);
    s1 += __shfl_xor_sync(0xffffffffu, s1, 16);
    s2 += __shfl_xor_sync(0xffffffffu, s2, 8);
    s2 += __shfl_xor_sync(0xffffffffu, s2, 16);
    s3 += __shfl_xor_sync(0xffffffffu, s3, 8);
    s3 += __shfl_xor_sync(0xffffffffu, s3, 16);
    q0 += __shfl_xor_sync(0xffffffffu, q0, 8);
    q0 += __shfl_xor_sync(0xffffffffu, q0, 16);
    q1 += __shfl_xor_sync(0xffffffffu, q1, 8);
    q1 += __shfl_xor_sync(0xffffffffu, q1, 16);
    q2 += __shfl_xor_sync(0xffffffffu, q2, 8);
    q2 += __shfl_xor_sync(0xffffffffu, q2, 16);
    q3 += __shfl_xor_sync(0xffffffffu, q3, 8);
    q3 += __shfl_xor_sync(0xffffffffu, q3, 16);
    {
        int warpId = t >> 5;
        if (lane < 8) {
            psum[warpId * 32 + lane * 4 + 0] = s0;
            psum[warpId * 32 + lane * 4 + 1] = s1;
            psum[warpId * 32 + lane * 4 + 2] = s2;
            psum[warpId * 32 + lane * 4 + 3] = s3;
            psq [warpId * 32 + lane * 4 + 0] = q0;
            psq [warpId * 32 + lane * 4 + 1] = q1;
            psq [warpId * 32 + lane * 4 + 2] = q2;
            psq [warpId * 32 + lane * 4 + 3] = q3;
        }
    }
    __syncthreads();

    // ======== Phase B: finish LN statistics (32 pixels) =====================
    if (t < 32) {
        float s = 0.f, q = 0.f;
        #pragma unroll
        for (int j = 0; j < 16; ++j) {
            s += psum[j * 32 + t];
            q += psq [j * 32 + t];
        }
        float m = s * (1.0f / 512.0f);
        float var = q * (1.0f / 512.0f) - m * m;
        mu[t] = m;
        rs[t] = rsqrtf(var + 1e-6f);
    }
    __syncthreads();

    // ======== Phase C: LN + fast GELU (tanh.approx), in place ===============
    {
        float4 m4 = *(const float4*)(mu + w4 * 4);
        float4 r4 = *(const float4*)(rs + w4 * 4);
        #pragma unroll 2
        for (int i = 0; i < 8; ++i) {
            int c = cgrp * 8 + i;
            float gg = ln_g[c];
            float bb = ln_b[c];
            float4 y = *(const float4*)(x1 + c * 32 + w4 * 4);
            y.x = (y.x - m4.x) * r4.x * gg + bb;
            y.y = (y.y - m4.y) * r4.y * gg + bb;
            y.z = (y.z - m4.z) * r4.z * gg + bb;
            y.w = (y.w - m4.w) * r4.w * gg + bb;
            y.x = gelu_fast(y.x);
            y.y = gelu_fast(y.y);
            y.z = gelu_fast(y.z);
            y.w = gelu_fast(y.w);
            *(float4*)(x1 + c * 32 + w4 * 4) = y;
        }
    }
    __syncthreads();

    // ======== Phase D: offset projection, 4o x 4w tiles, f32x2 ==============
    {
        const int g4   = t & 7;          // w-quad
        const int og   = (t >> 3) & 7;   // o-quad
        const int part = t >> 6;         // c-part, 64 channels each
        const float4* wt = (const float4*)g_offw_t;    // [c*8 + og]
        ull a00 = 0, a01 = 0, a10 = 0, a11 = 0;
        ull a20 = 0, a21 = 0, a30 = 0, a31 = 0;
        int cb = part * 64;
        #pragma unroll 4
        for (int ci = 0; ci < 64; ++ci) {
            int c = cb + ci;
            ulonglong2 xv = *(const ulonglong2*)(x1 + c * 32 + g4 * 4);
            float4 wv = __ldg(wt + c * 8 + og);
            ull w0 = pack2(wv.x, wv.x);
            ull w1 = pack2(wv.y, wv.y);
            ull w2 = pack2(wv.z, wv.z);
            ull w3 = pack2(wv.w, wv.w);
            a00 = fma2(w0, xv.x, a00); a01 = fma2(w0, xv.y, a01);
            a10 = fma2(w1, xv.x, a10); a11 = fma2(w1, xv.y, a11);
            a20 = fma2(w2, xv.x, a20); a21 = fma2(w2, xv.y, a21);
            a30 = fma2(w3, xv.x, a30); a31 = fma2(w3, xv.y, a31);
        }
        float* pp = offsP + part * 1024 + (og * 4) * 32 + g4 * 4;
        ((ull*)(pp +  0))[0] = a00; ((ull*)(pp +  0))[1] = a01;
        ((ull*)(pp + 32))[0] = a10; ((ull*)(pp + 32))[1] = a11;
        ((ull*)(pp + 64))[0] = a20; ((ull*)(pp + 64))[1] = a21;
        ((ull*)(pp + 96))[0] = a30; ((ull*)(pp + 96))[1] = a31;
    }
    __syncthreads();

    // reduce 8 partials -> offs in offsP[0:1024], add bias
    {
        #pragma unroll
        for (int r = 0; r < 2; ++r) {
            int idx = t + r * 512;
            int o = idx >> 5;
            float s = offsP[idx];
            #pragma unroll
            for (int p = 1; p < 8; ++p) s += offsP[p * 1024 + idx];
            offsP[idx] = s + __ldg(off_b + o);
        }
    }
    __syncthreads();

    // ======== Phase E0: per-sample bilinear params ===========================
    {
        const int S = t;            // 0..511
        const int g = S >> 5;
        const int w = S & 31;
        float px = (float)(wbase + w) + offsP[(2 * g + 0) * 32 + w];
        float py = (float)h           + offsP[(2 * g + 1) * 32 + w];
        float x0f = floorf(px);
        float y0f = floorf(py);
        float fx = px - x0f;
        float fy = py - y0f;
        int x0 = (int)x0f;
        int y0 = (int)y0f;
        float vx0 = (x0f >= 0.f       && x0f <= 63.f)       ? 1.f : 0.f;
        float vx1 = (x0f + 1.f >= 0.f && x0f + 1.f <= 63.f) ? 1.f : 0.f;
        float vy0 = (y0f >= 0.f       && y0f <= 63.f)       ? 1.f : 0.f;
        float vy1 = (y0f + 1.f >= 0.f && y0f + 1.f <= 63.f) ? 1.f : 0.f;
        int xc0 = min(max(x0, 0), 63);
        int xc1 = min(max(x0 + 1, 0), 63);
        int yc0 = min(max(y0, 0), 63);
        int yc1 = min(max(y0 + 1, 0), 63);
        float* q = sp + S * 8;
        q[0] = (1.f - fx) * (1.f - fy) * vx0 * vy0;
        q[1] = fx * (1.f - fy) * vx1 * vy0;
        q[2] = (1.f - fx) * fy * vx0 * vy1;
        q[3] = fx * fy * vx1 * vy1;
        int* qi = (int*)(q + 4);
        qi[0] = (yc0 * 64 + xc0) * 512;
        qi[1] = (yc0 * 64 + xc1) * 512;
        qi[2] = (yc1 * 64 + xc0) * 512;
        qi[3] = (yc1 * 64 + xc1) * 512;
    }
    __syncthreads();

    // ======== Phase E: coalesced bilinear gather (8 lanes per sample) =======
    {
        const int wp = t >> 5;        // warp 0..15
        const int s  = (t >> 3) & 3;  // sample within warp
        const int e  = t & 7;         // quad within GC=32
        const float* inL_n = inL + (size_t)n * H_ * W_ * C_;
        #pragma unroll
        for (int k = 0; k < 8; ++k) {
            int S = k * 64 + wp * 4 + s;    // 0..511
            int g = S >> 5;
            int w = S & 31;
            float4 wgt = *(const float4*)(sp + S * 8);
            int4  ofs  = *(const int4*) (sp + S * 8 + 4);
            const float* bp = inL_n + g * 32 + e * 4;
            ulonglong2 a = *(const ulonglong2*)(bp + ofs.x);
            ulonglong2 b = *(const ulonglong2*)(bp + ofs.y);
            ulonglong2 c = *(const ulonglong2*)(bp + ofs.z);
            ulonglong2 d = *(const ulonglong2*)(bp + ofs.w);
            ull w00 = pack2(wgt.x, wgt.x);
            ull w10 = pack2(wgt.y, wgt.y);
            ull w01 = pack2(wgt.z, wgt.z);
            ull w11 = pack2(wgt.w, wgt.w);
            ull rlo = mul2(w00, a.x);
            rlo = fma2(w10, b.x, rlo);
            rlo = fma2(w01, c.x, rlo);
            rlo = fma2(w11, d.x, rlo);
            ull rhi = mul2(w00, a.y);
            rhi = fma2(w10, b.y, rhi);
            rhi = fma2(w01, c.y, rhi);
            rhi = fma2(w11, d.y, rhi);
            float r0, r1, r2, r3;
            unpack2(rlo, r0, r1);
            unpack2(rhi, r2, r3);
            int crow = g * 32 + e * 4;
            stage[(crow + 0) * 33 + w] = r0;
            stage[(crow + 1) * 33 + w] = r1;
            stage[(crow + 2) * 33 + w] = r2;
            stage[(crow + 3) * 33 + w] = r3;
        }
    }
    __syncthreads();

    // ======== Phase F: coalesced copy-out ====================================
    {
        float* outp = out + (size_t)n * C_ * H_ * W_ + (size_t)h * W_ + wbase;
        #pragma unroll
        for (int k = 0; k < 8; ++k) {
            int c = (t >> 3) + k * 64;
            float4 r;
            r.x = stage[c * 33 + w4 * 4 + 0];
            r.y = stage[c * 33 + w4 * 4 + 1];
            r.z = stage[c * 33 + w4 * 4 + 2];
            r.w = stage[c * 33 + w4 * 4 + 3];
            *(float4*)(outp + (size_t)c * (H_ * W_) + w4 * 4) = r;
        }
    }
}

extern "C" void kernel_launch(void* const* d_in, const int* in_sizes, int n_in,
                              void* d_out, int out_size)
{
    (void)in_sizes; (void)n_in; (void)out_size;
    const float* in0   = (const float*)d_in[0];
    const float* inL   = (const float*)d_in[1];
    const float* dw_w  = (const float*)d_in[2];
    const float* dw_b  = (const float*)d_in[3];
    const float* ln_g  = (const float*)d_in[4];
    const float* ln_b  = (const float*)d_in[5];
    const float* off_w = (const float*)d_in[6];
    const float* off_b = (const float*)d_in[7];
    float* out = (float*)d_out;

    transpose_offw_kernel<<<16, 1024>>>(off_w);

    const int smem_bytes = SMEM_FLOATS * sizeof(float);   // 100608
    cudaFuncSetAttribute(das_fused_kernel,
                         cudaFuncAttributeMaxDynamicSharedMemorySize, smem_bytes);

    dim3 grid(2, H_, N_);
    das_fused_kernel<<<grid, 512, smem_bytes>>>(in0, inL, dw_w, dw_b,
                                                ln_g, ln_b, off_b, out);
}